// round 1
// baseline (speedup 1.0000x reference)
#include <cuda_runtime.h>
#include <cstdint>

// Problem sizes (fixed by the reference)
#define MM 8192      // rows of adj / x / out
#define KK 8192      // inner dim of GEMM1 (adj cols)
#define DD 512       // feature dim

// 16 MB scratch for agg = adj @ x  (static __device__ array: allowed)
__device__ float g_agg[(size_t)MM * DD];

__device__ __forceinline__ float f2tf(float x) {
    uint32_t r;
    asm("cvt.rna.tf32.f32 %0, %1;" : "=r"(r) : "f"(x));
    return __uint_as_float(r);
}

__device__ __forceinline__ void mma_tf32(float* d, const uint32_t* a, const uint32_t* b) {
    asm volatile(
        "mma.sync.aligned.m16n8k8.row.col.f32.tf32.tf32.f32 "
        "{%0,%1,%2,%3}, {%4,%5,%6,%7}, {%8,%9}, {%0,%1,%2,%3};\n"
        : "+f"(d[0]), "+f"(d[1]), "+f"(d[2]), "+f"(d[3])
        : "r"(a[0]), "r"(a[1]), "r"(a[2]), "r"(a[3]),
          "r"(b[0]), "r"(b[1]));
}

// ---------------------------------------------------------------------------
// GEMM1: g_agg[M,D] = adj[M,K] @ x[K,D]
// CTA tile 128x128, BK=32. 256 threads = 8 warps (4 along M x 2 along N).
// Warp tile 32(M) x 64(N): 2 m-frags x 8 n-frags of m16n8k8.
// ---------------------------------------------------------------------------
__global__ void __launch_bounds__(256, 2)
gemm1_kernel(const float* __restrict__ A, const float* __restrict__ B) {
    __shared__ float As[128][36];   // [m][k], ld=36 -> conflict-free frag loads
    __shared__ float Bs[32][136];   // [k][n], ld=136 -> conflict-free frag loads

    const int tid  = threadIdx.x;
    const int warp = tid >> 5;
    const int lane = tid & 31;
    const int g    = lane >> 2;     // groupID 0..7
    const int tg   = lane & 3;      // threadID-in-group 0..3
    const int wm   = warp & 3;      // warp row 0..3  (M)
    const int wn   = warp >> 2;     // warp col 0..1  (N)

    const int m0 = blockIdx.y * 128;
    const int n0 = blockIdx.x * 128;

    float acc[2][8][4];
    #pragma unroll
    for (int i = 0; i < 2; i++)
        #pragma unroll
        for (int j = 0; j < 8; j++)
            #pragma unroll
            for (int c = 0; c < 4; c++) acc[i][j][c] = 0.0f;

    // gmem->smem load mappings
    const int ar = tid >> 3;   // 0..31  A tile row   (stride 32)
    const int ac = tid & 7;    // 0..7   A float4 col
    const int br = tid >> 5;   // 0..7   B tile row   (stride 8)
    const int bc = tid & 31;   // 0..31  B float4 col

    for (int kt = 0; kt < KK; kt += 32) {
        __syncthreads();
        // Load A tile 128x32
        #pragma unroll
        for (int i = 0; i < 4; i++) {
            int r = ar + i * 32;
            float4 v = *reinterpret_cast<const float4*>(
                &A[(size_t)(m0 + r) * KK + kt + ac * 4]);
            As[r][ac * 4 + 0] = f2tf(v.x);
            As[r][ac * 4 + 1] = f2tf(v.y);
            As[r][ac * 4 + 2] = f2tf(v.z);
            As[r][ac * 4 + 3] = f2tf(v.w);
        }
        // Load B tile 32x128
        #pragma unroll
        for (int i = 0; i < 4; i++) {
            int r = br + i * 8;
            float4 v = *reinterpret_cast<const float4*>(
                &B[(size_t)(kt + r) * DD + n0 + bc * 4]);
            Bs[r][bc * 4 + 0] = f2tf(v.x);
            Bs[r][bc * 4 + 1] = f2tf(v.y);
            Bs[r][bc * 4 + 2] = f2tf(v.z);
            Bs[r][bc * 4 + 3] = f2tf(v.w);
        }
        __syncthreads();

        #pragma unroll
        for (int ks = 0; ks < 4; ks++) {
            const int kk = ks * 8;
            uint32_t a[2][4];
            uint32_t b[8][2];
            #pragma unroll
            for (int i = 0; i < 2; i++) {
                int mb = wm * 32 + i * 16;
                a[i][0] = __float_as_uint(As[mb + g    ][kk + tg    ]);
                a[i][1] = __float_as_uint(As[mb + g + 8][kk + tg    ]);
                a[i][2] = __float_as_uint(As[mb + g    ][kk + tg + 4]);
                a[i][3] = __float_as_uint(As[mb + g + 8][kk + tg + 4]);
            }
            #pragma unroll
            for (int j = 0; j < 8; j++) {
                int nb = wn * 64 + j * 8 + g;
                b[j][0] = __float_as_uint(Bs[kk + tg    ][nb]);
                b[j][1] = __float_as_uint(Bs[kk + tg + 4][nb]);
            }
            #pragma unroll
            for (int i = 0; i < 2; i++)
                #pragma unroll
                for (int j = 0; j < 8; j++)
                    mma_tf32(acc[i][j], a[i], b[j]);
        }
    }

    // Epilogue: write agg
    #pragma unroll
    for (int i = 0; i < 2; i++) {
        #pragma unroll
        for (int j = 0; j < 8; j++) {
            int m = m0 + wm * 32 + i * 16 + g;
            int n = n0 + wn * 64 + j * 8 + tg * 2;
            float2 v0 = make_float2(acc[i][j][0], acc[i][j][1]);
            float2 v1 = make_float2(acc[i][j][2], acc[i][j][3]);
            *reinterpret_cast<float2*>(&g_agg[(size_t)m * DD + n])       = v0;
            *reinterpret_cast<float2*>(&g_agg[(size_t)(m + 8) * DD + n]) = v1;
        }
    }
}

// ---------------------------------------------------------------------------
// GEMM2: out[M,D] = relu(g_agg[M,D] @ W^T + b);  W is [out=D, in=D] row-major
// out[m][n] = sum_k agg[m][k] * W[n][k]  -> B tile Bs[k][n] = W[n0+n][k0+k]
// ---------------------------------------------------------------------------
__global__ void __launch_bounds__(256, 2)
gemm2_kernel(const float* __restrict__ W, const float* __restrict__ bias,
             float* __restrict__ out) {
    __shared__ float As[128][36];
    __shared__ float Bs[32][136];

    const int tid  = threadIdx.x;
    const int warp = tid >> 5;
    const int lane = tid & 31;
    const int g    = lane >> 2;
    const int tg   = lane & 3;
    const int wm   = warp & 3;
    const int wn   = warp >> 2;

    const int m0 = blockIdx.y * 128;
    const int n0 = blockIdx.x * 128;

    float acc[2][8][4];
    #pragma unroll
    for (int i = 0; i < 2; i++)
        #pragma unroll
        for (int j = 0; j < 8; j++)
            #pragma unroll
            for (int c = 0; c < 4; c++) acc[i][j][c] = 0.0f;

    const int ar = tid >> 3;   // 0..31
    const int ac = tid & 7;    // 0..7
    const int wr = tid >> 3;   // 0..31  W row within n-tile (stride 32)
    const int wq = tid & 7;    // 0..7   W float4 col within k-tile

    for (int kt = 0; kt < DD; kt += 32) {
        __syncthreads();
        // A tile 128x32 from g_agg (K = DD = 512)
        #pragma unroll
        for (int i = 0; i < 4; i++) {
            int r = ar + i * 32;
            float4 v = *reinterpret_cast<const float4*>(
                &g_agg[(size_t)(m0 + r) * DD + kt + ac * 4]);
            As[r][ac * 4 + 0] = f2tf(v.x);
            As[r][ac * 4 + 1] = f2tf(v.y);
            As[r][ac * 4 + 2] = f2tf(v.z);
            As[r][ac * 4 + 3] = f2tf(v.w);
        }
        // B tile: transpose of W panel. Read W rows coalesced, store transposed.
        #pragma unroll
        for (int i = 0; i < 4; i++) {
            int n = wr + i * 32;  // 0..127
            float4 v = *reinterpret_cast<const float4*>(
                &W[(size_t)(n0 + n) * DD + kt + wq * 4]);
            Bs[wq * 4 + 0][n] = f2tf(v.x);
            Bs[wq * 4 + 1][n] = f2tf(v.y);
            Bs[wq * 4 + 2][n] = f2tf(v.z);
            Bs[wq * 4 + 3][n] = f2tf(v.w);
        }
        __syncthreads();

        #pragma unroll
        for (int ks = 0; ks < 4; ks++) {
            const int kk = ks * 8;
            uint32_t a[2][4];
            uint32_t b[8][2];
            #pragma unroll
            for (int i = 0; i < 2; i++) {
                int mb = wm * 32 + i * 16;
                a[i][0] = __float_as_uint(As[mb + g    ][kk + tg    ]);
                a[i][1] = __float_as_uint(As[mb + g + 8][kk + tg    ]);
                a[i][2] = __float_as_uint(As[mb + g    ][kk + tg + 4]);
                a[i][3] = __float_as_uint(As[mb + g + 8][kk + tg + 4]);
            }
            #pragma unroll
            for (int j = 0; j < 8; j++) {
                int nb = wn * 64 + j * 8 + g;
                b[j][0] = __float_as_uint(Bs[kk + tg    ][nb]);
                b[j][1] = __float_as_uint(Bs[kk + tg + 4][nb]);
            }
            #pragma unroll
            for (int i = 0; i < 2; i++)
                #pragma unroll
                for (int j = 0; j < 8; j++)
                    mma_tf32(acc[i][j], a[i], b[j]);
        }
    }

    // Epilogue: bias + ReLU
    #pragma unroll
    for (int i = 0; i < 2; i++) {
        #pragma unroll
        for (int j = 0; j < 8; j++) {
            int m = m0 + wm * 32 + i * 16 + g;
            int n = n0 + wn * 64 + j * 8 + tg * 2;
            float b0 = bias[n], b1 = bias[n + 1];
            float2 v0 = make_float2(fmaxf(acc[i][j][0] + b0, 0.0f),
                                    fmaxf(acc[i][j][1] + b1, 0.0f));
            float2 v1 = make_float2(fmaxf(acc[i][j][2] + b0, 0.0f),
                                    fmaxf(acc[i][j][3] + b1, 0.0f));
            *reinterpret_cast<float2*>(&out[(size_t)m * DD + n])       = v0;
            *reinterpret_cast<float2*>(&out[(size_t)(m + 8) * DD + n]) = v1;
        }
    }
}

extern "C" void kernel_launch(void* const* d_in, const int* in_sizes, int n_in,
                              void* d_out, int out_size) {
    const float* x   = (const float*)d_in[0];  // [8192, 512]
    const float* adj = (const float*)d_in[1];  // [8192, 8192]
    const float* W   = (const float*)d_in[2];  // [512, 512]
    const float* b   = (const float*)d_in[3];  // [512]
    float* out = (float*)d_out;                // [8192, 512]

    dim3 grid(DD / 128, MM / 128);  // (4, 64): x-major over N-tiles -> adj L2 reuse
    gemm1_kernel<<<grid, 256>>>(adj, x);
    gemm2_kernel<<<grid, 256>>>(W, b, out);
}